// round 1
// baseline (speedup 1.0000x reference)
#include <cuda_runtime.h>
#include <cstdint>
#include <cstddef>

// Problem constants
constexpr int PB = 8, PS = 1024, PD = 768, PH = 12, PHD = 64;
constexpr size_t QKV_ELEMS = (size_t)PB * PH * PS * PHD;        // 6,291,456
constexpr size_t OUT_ELEMS = (size_t)PB * PS * PD;              // 6,291,456
// prob_attn elems = B*H*S*S = 100,663,296

// Scratch (no allocations allowed -> __device__ globals)
__device__ float g_q[QKV_ELEMS];
__device__ float g_k[QKV_ELEMS];
__device__ float g_v[QKV_ELEMS];
__device__ int   g_mask_mode;   // 0 = uint8/bool, 1 = int32, 2 = float32

// ---------------------------------------------------------------------------
// Mask dtype probe: scan first 2048 words. float32 bool -> words in {0, 0x3F800000}.
// int32 bool -> words in {0,1}. packed uint8 bool -> words with bytes 0/1 (values
// like 0x00010001 > 1). Deterministic per input.
// ---------------------------------------------------------------------------
__global__ void detect_mask_kernel(const void* __restrict__ mask) {
    __shared__ int sawFloat, sawOther;
    if (threadIdx.x == 0) { sawFloat = 0; sawOther = 0; }
    __syncthreads();
    const unsigned int* w = (const unsigned int*)mask;
    int lf = 0, lo = 0;
    for (int i = threadIdx.x; i < 2048; i += blockDim.x) {
        unsigned int x = w[i];
        if (x == 0x3F800000u) lf = 1;
        else if (x > 1u) lo = 1;
    }
    if (lf) atomicOr(&sawFloat, 1);
    if (lo) atomicOr(&sawOther, 1);
    __syncthreads();
    if (threadIdx.x == 0) g_mask_mode = sawFloat ? 2 : (sawOther ? 0 : 1);
}

__device__ __forceinline__ bool read_mask(const void* m, size_t idx, int mode) {
    if (mode == 0) return ((const unsigned char*)m)[idx] != 0;
    if (mode == 1) return ((const int*)m)[idx] != 0;
    return ((const float*)m)[idx] != 0.0f;
}

// ---------------------------------------------------------------------------
// Kernel 1: fused Q/K/V projections. Y = X @ W^T + bias, scattered to
// [b][h][s][hd]. NT GEMM, M=8192, N=768, K=768. Tile 128x128x16, 256 threads,
// 8x8 microtile, register prefetch.
// ---------------------------------------------------------------------------
__global__ __launch_bounds__(256, 2) void proj_kernel(
    const float* __restrict__ Xq, const float* __restrict__ Xk, const float* __restrict__ Xv,
    const float* __restrict__ Wq, const float* __restrict__ Wk, const float* __restrict__ Wv,
    const float* __restrict__ bq, const float* __restrict__ bk, const float* __restrict__ bv)
{
    const int z = blockIdx.z;
    const float* X    = (z == 0) ? Xq : (z == 1) ? Xk : Xv;
    const float* W    = (z == 0) ? Wq : (z == 1) ? Wk : Wv;
    const float* bias = (z == 0) ? bq : (z == 1) ? bk : bv;
    float* out        = (z == 0) ? g_q : (z == 1) ? g_k : g_v;

    __shared__ float As[16][136];   // [k][m], padded
    __shared__ float Bs[16][136];   // [k][n], padded

    const int tid = threadIdx.x;
    const int tx = tid & 15;        // n microtile group
    const int ty = tid >> 4;        // m microtile group
    const int m0 = blockIdx.y * 128;
    const int n0 = blockIdx.x * 128;

    float acc[8][8];
#pragma unroll
    for (int i = 0; i < 8; i++)
#pragma unroll
        for (int j = 0; j < 8; j++) acc[i][j] = 0.0f;

    const int lrow = tid >> 1;          // 0..127
    const int lk   = (tid & 1) * 8;     // 0 or 8
    const float* Arow = X + (size_t)(m0 + lrow) * PD + lk;
    const float* Brow = W + (size_t)(n0 + lrow) * PD + lk;

    float4 pa0 = *(const float4*)(Arow);
    float4 pa1 = *(const float4*)(Arow + 4);
    float4 pb0 = *(const float4*)(Brow);
    float4 pb1 = *(const float4*)(Brow + 4);

    for (int k0 = 0; k0 < PD; k0 += 16) {
        __syncthreads();
        As[lk + 0][lrow] = pa0.x; As[lk + 1][lrow] = pa0.y;
        As[lk + 2][lrow] = pa0.z; As[lk + 3][lrow] = pa0.w;
        As[lk + 4][lrow] = pa1.x; As[lk + 5][lrow] = pa1.y;
        As[lk + 6][lrow] = pa1.z; As[lk + 7][lrow] = pa1.w;
        Bs[lk + 0][lrow] = pb0.x; Bs[lk + 1][lrow] = pb0.y;
        Bs[lk + 2][lrow] = pb0.z; Bs[lk + 3][lrow] = pb0.w;
        Bs[lk + 4][lrow] = pb1.x; Bs[lk + 5][lrow] = pb1.y;
        Bs[lk + 6][lrow] = pb1.z; Bs[lk + 7][lrow] = pb1.w;
        __syncthreads();
        if (k0 + 16 < PD) {  // prefetch next K-slab into registers
            pa0 = *(const float4*)(Arow + k0 + 16);
            pa1 = *(const float4*)(Arow + k0 + 20);
            pb0 = *(const float4*)(Brow + k0 + 16);
            pb1 = *(const float4*)(Brow + k0 + 20);
        }
#pragma unroll
        for (int kk = 0; kk < 16; kk++) {
            float a[8], bb[8];
            *(float4*)&a[0]  = *(const float4*)&As[kk][ty * 8];
            *(float4*)&a[4]  = *(const float4*)&As[kk][ty * 8 + 4];
            *(float4*)&bb[0] = *(const float4*)&Bs[kk][tx * 8];
            *(float4*)&bb[4] = *(const float4*)&Bs[kk][tx * 8 + 4];
#pragma unroll
            for (int i = 0; i < 8; i++)
#pragma unroll
                for (int j = 0; j < 8; j++)
                    acc[i][j] = fmaf(a[i], bb[j], acc[i][j]);
        }
    }

    // epilogue: scatter to [b][h][s][hd] (+bias)
    const int ncol0 = n0 + tx * 8;
    const int h  = ncol0 >> 6;          // 8-col microtile never crosses a head
    const int hd = ncol0 & 63;
    float bi[8];
#pragma unroll
    for (int j = 0; j < 8; j++) bi[j] = bias[ncol0 + j];
#pragma unroll
    for (int i = 0; i < 8; i++) {
        const int m = m0 + ty * 8 + i;
        const int b = m >> 10;
        const int s = m & 1023;
        float* dst = out + (((size_t)(b * PH + h)) * PS + s) * PHD + hd;
        float4 o0, o1;
        o0.x = acc[i][0] + bi[0]; o0.y = acc[i][1] + bi[1];
        o0.z = acc[i][2] + bi[2]; o0.w = acc[i][3] + bi[3];
        o1.x = acc[i][4] + bi[4]; o1.y = acc[i][5] + bi[5];
        o1.z = acc[i][6] + bi[6]; o1.w = acc[i][7] + bi[7];
        *(float4*)(dst)     = o0;
        *(float4*)(dst + 4) = o1;
    }
}

// ---------------------------------------------------------------------------
// Kernel 2: per (b, 16-row q-tile): compute rel-softmax + mask ONCE, then loop
// all 12 heads: S = QK^T/8 (masked), softmax, combine with rel_attn, write
// prob_attn. Dynamic smem 184,832 B.
// smem layout (bytes):
//   relp  [16][1024] f32   @ 0        (65536)
//   sbuf  [16][1024] f32   @ 65536    (65536)
//   kts   [128][65]  f32   @ 131072   (33280)   k-major, pad 65 for banks
//   qtsT  [64][16]   f32   @ 164352   (4096)    d-major
//   msk   [16][1024] u8    @ 168448   (16384)
// ---------------------------------------------------------------------------
constexpr int QT = 16, KC = 128;
constexpr size_t K2_SMEM = 184832;

__global__ void attn_scores_kernel(const float* __restrict__ rel,
                                   const void* __restrict__ mask,
                                   const float* __restrict__ l1p,
                                   float* __restrict__ prob)
{
    extern __shared__ unsigned char smem[];
    float* relp = (float*)smem;
    float* sbuf = (float*)(smem + 65536);
    float* kts  = (float*)(smem + 131072);
    float* qtsT = (float*)(smem + 164352);
    unsigned char* msk = smem + 168448;

    const int tid  = threadIdx.x;
    const int lane = tid & 31;
    const int warp = tid >> 5;
    const int b  = blockIdx.y;
    const int q0 = blockIdx.x * QT;
    const int mmode = g_mask_mode;
    const float l1 = *l1p;
    const float w0 = 1.0f - l1;

    // Phase 0: mask tile + rel_attn tile (warp per row, rows warp and warp+8)
#pragma unroll
    for (int rr = 0; rr < 2; rr++) {
        const int r = warp + rr * 8;
        const size_t rbase = ((size_t)b * PS + q0 + r) * PS;
        float mx = -3.0e38f;
        for (int c = lane; c < PS; c += 32) {
            const bool m = read_mask(mask, rbase + c, mmode);
            msk[r * PS + c] = m ? 1 : 0;
            const float v = rel[rbase + c];
            const float relm = m ? v : 0.0f;
            const float logit = (relm == 0.0f) ? -10000.0f : relm;
            relp[r * PS + c] = logit;
            mx = fmaxf(mx, logit);
        }
#pragma unroll
        for (int o = 16; o; o >>= 1) mx = fmaxf(mx, __shfl_xor_sync(0xffffffffu, mx, o));
        float sum = 0.0f;
        for (int c = lane; c < PS; c += 32) {
            const float e = __expf(relp[r * PS + c] - mx);
            relp[r * PS + c] = e;
            sum += e;
        }
#pragma unroll
        for (int o = 16; o; o >>= 1) sum += __shfl_xor_sync(0xffffffffu, sum, o);
        const float inv = 1.0f / sum;
        for (int c = lane; c < PS; c += 32) relp[r * PS + c] *= inv;
    }
    __syncthreads();

    for (int h = 0; h < PH; h++) {
        // load Q tile, transposed to [d][q]
        const size_t qbase = (((size_t)b * PH + h) * PS + q0) * PHD;
#pragma unroll
        for (int it = 0; it < 4; it++) {
            const int i = tid + it * 256;
            const int r = i >> 6, hd = i & 63;
            qtsT[hd * QT + r] = g_q[qbase + (size_t)r * PHD + hd];
        }
        const size_t kbase = (((size_t)b * PH + h) * PS) * PHD;

        for (int kc0 = 0; kc0 < PS; kc0 += KC) {
            __syncthreads();  // publishes qtsT (1st iter) / protects kts reuse
            // load K chunk [128][65] (k-major, padded)
            const float4* src = (const float4*)(g_k + kbase + (size_t)kc0 * PHD);
#pragma unroll
            for (int it = 0; it < 8; it++) {
                const int i4 = tid + it * 256;            // 0..2047
                const int kr = i4 >> 4, hd0 = (i4 & 15) << 2;
                const float4 vv = src[(size_t)kr * 16 + (hd0 >> 2)];
                float* drow = kts + kr * 65 + hd0;
                drow[0] = vv.x; drow[1] = vv.y; drow[2] = vv.z; drow[3] = vv.w;
            }
            __syncthreads();
            // compute 16 x 128 scores: 4 qg x 64 kg, micro 4q x 2k
            const int kg = tid & 63, qg = tid >> 6;
            float acc[4][2];
#pragma unroll
            for (int i = 0; i < 4; i++) { acc[i][0] = 0.0f; acc[i][1] = 0.0f; }
            const float* kr0 = kts + (kg * 2) * 65;
            const float* kr1 = kr0 + 65;
            const float* qcol = qtsT + qg * 4;
#pragma unroll 16
            for (int d = 0; d < PHD; d++) {
                const float4 qv = *(const float4*)(qcol + d * QT);
                const float k0v = kr0[d], k1v = kr1[d];
                acc[0][0] = fmaf(qv.x, k0v, acc[0][0]); acc[0][1] = fmaf(qv.x, k1v, acc[0][1]);
                acc[1][0] = fmaf(qv.y, k0v, acc[1][0]); acc[1][1] = fmaf(qv.y, k1v, acc[1][1]);
                acc[2][0] = fmaf(qv.z, k0v, acc[2][0]); acc[2][1] = fmaf(qv.z, k1v, acc[2][1]);
                acc[3][0] = fmaf(qv.w, k0v, acc[3][0]); acc[3][1] = fmaf(qv.w, k1v, acc[3][1]);
            }
#pragma unroll
            for (int i = 0; i < 4; i++) {
                const int q = qg * 4 + i;
#pragma unroll
                for (int j = 0; j < 2; j++) {
                    const int kcol = kc0 + kg * 2 + j;
                    const float s = acc[i][j] * 0.125f;
                    sbuf[q * PS + kcol] = msk[q * PS + kcol] ? -1.0e9f : s;
                }
            }
        }
        __syncthreads();
        // softmax + combine + write prob_attn
        const size_t pbase = (((size_t)b * PH + h) * PS + q0) * PS;
#pragma unroll
        for (int rr = 0; rr < 2; rr++) {
            const int r = warp + rr * 8;
            float mx = -3.0e38f;
            for (int c = lane; c < PS; c += 32) mx = fmaxf(mx, sbuf[r * PS + c]);
#pragma unroll
            for (int o = 16; o; o >>= 1) mx = fmaxf(mx, __shfl_xor_sync(0xffffffffu, mx, o));
            float sum = 0.0f;
            for (int c = lane; c < PS; c += 32) {
                const float e = __expf(sbuf[r * PS + c] - mx);
                sbuf[r * PS + c] = e;
                sum += e;
            }
#pragma unroll
            for (int o = 16; o; o >>= 1) sum += __shfl_xor_sync(0xffffffffu, sum, o);
            const float inv = 1.0f / sum;
            for (int c = lane; c < PS; c += 32)
                prob[pbase + (size_t)r * PS + c] = w0 * (sbuf[r * PS + c] * inv)
                                                 + l1 * relp[r * PS + c];
        }
        __syncthreads();
    }
}

// ---------------------------------------------------------------------------
// Kernel 3: out = prob @ V per (b,h). M=1024, N=64, K=1024. Tile 128x64x32,
// 256 threads, micro 8q x 4n. Writes out[b][s][h*64+hd].
// ---------------------------------------------------------------------------
__global__ __launch_bounds__(256, 2) void pv_kernel(const float* __restrict__ prob,
                                                    float* __restrict__ outp)
{
    __shared__ float pt[32][136];   // [k][q] transposed, padded
    __shared__ float vt[32][64];    // [k][n]

    const int bh = blockIdx.y;
    const int b = bh / PH, h = bh % PH;
    const int q0 = blockIdx.x * 128;
    const int tid = threadIdx.x;
    const int ng = tid & 15, qg = tid >> 4;

    float acc[8][4];
#pragma unroll
    for (int i = 0; i < 8; i++)
#pragma unroll
        for (int j = 0; j < 4; j++) acc[i][j] = 0.0f;

    const size_t pbase = ((size_t)bh * PS + q0) * PS;
    const size_t vbase = (size_t)bh * PS * PHD;

    for (int kc0 = 0; kc0 < PS; kc0 += 32) {
        __syncthreads();
#pragma unroll
        for (int it = 0; it < 4; it++) {            // pt: 128q x 32k
            const int i4 = tid + it * 256;          // 0..1023
            const int q = i4 >> 3, kq = (i4 & 7) << 2;
            const float4 v = *(const float4*)(prob + pbase + (size_t)q * PS + kc0 + kq);
            pt[kq + 0][q] = v.x; pt[kq + 1][q] = v.y;
            pt[kq + 2][q] = v.z; pt[kq + 3][q] = v.w;
        }
#pragma unroll
        for (int it = 0; it < 2; it++) {            // vt: 32k x 64n
            const int i4 = tid + it * 256;          // 0..511
            const int kr = i4 >> 4, n = (i4 & 15) << 2;
            *(float4*)&vt[kr][n] = *(const float4*)(g_v + vbase + (size_t)(kc0 + kr) * PHD + n);
        }
        __syncthreads();
#pragma unroll 8
        for (int kk = 0; kk < 32; kk++) {
            float p[8];
            *(float4*)&p[0] = *(const float4*)&pt[kk][qg * 8];
            *(float4*)&p[4] = *(const float4*)&pt[kk][qg * 8 + 4];
            const float4 vv = *(const float4*)&vt[kk][ng * 4];
#pragma unroll
            for (int i = 0; i < 8; i++) {
                acc[i][0] = fmaf(p[i], vv.x, acc[i][0]);
                acc[i][1] = fmaf(p[i], vv.y, acc[i][1]);
                acc[i][2] = fmaf(p[i], vv.z, acc[i][2]);
                acc[i][3] = fmaf(p[i], vv.w, acc[i][3]);
            }
        }
    }
#pragma unroll
    for (int i = 0; i < 8; i++) {
        const int q = q0 + qg * 8 + i;
        float4 o;
        o.x = acc[i][0]; o.y = acc[i][1]; o.z = acc[i][2]; o.w = acc[i][3];
        *(float4*)&outp[((size_t)b * PS + q) * PD + h * PHD + ng * 4] = o;
    }
}

// ---------------------------------------------------------------------------
extern "C" void kernel_launch(void* const* d_in, const int* in_sizes, int n_in,
                              void* d_out, int out_size) {
    const float* query = (const float*)d_in[0];
    const float* key   = (const float*)d_in[1];
    const float* value = (const float*)d_in[2];
    const float* rel   = (const float*)d_in[3];
    const void*  mask  = d_in[4];
    const float* l1    = (const float*)d_in[5];
    const float* Wq    = (const float*)d_in[6];
    const float* bq    = (const float*)d_in[7];
    const float* Wk    = (const float*)d_in[8];
    const float* bk    = (const float*)d_in[9];
    const float* Wv    = (const float*)d_in[10];
    const float* bv    = (const float*)d_in[11];

    float* outp = (float*)d_out;
    float* prob = outp + OUT_ELEMS;

    detect_mask_kernel<<<1, 256>>>(mask);

    dim3 g1(PD / 128, (PB * PS) / 128, 3);     // (6, 64, 3)
    proj_kernel<<<g1, 256>>>(query, key, value, Wq, Wk, Wv, bq, bk, bv);

    cudaFuncSetAttribute(attn_scores_kernel,
                         cudaFuncAttributeMaxDynamicSharedMemorySize, (int)K2_SMEM);
    dim3 g2(PS / QT, PB);                      // (64, 8)
    attn_scores_kernel<<<g2, 256, K2_SMEM>>>(rel, mask, l1, prob);

    dim3 g3(PS / 128, PB * PH);                // (8, 96)
    pv_kernel<<<g3, 256>>>(prob, outp);
}

// round 4
// speedup vs baseline: 1.0368x; 1.0368x over previous
#include <cuda_runtime.h>
#include <cstdint>
#include <cstddef>

// Problem constants
constexpr int PB = 8, PS = 1024, PD = 768, PH = 12, PHD = 64;
constexpr size_t QKV_ELEMS = (size_t)PB * PH * PS * PHD;        // 6,291,456
constexpr size_t OUT_ELEMS = (size_t)PB * PS * PD;              // 6,291,456

// Scratch (no allocations allowed -> __device__ globals)
__device__ float g_q[QKV_ELEMS];
__device__ float g_k[QKV_ELEMS];
__device__ float g_v[QKV_ELEMS];
__device__ int   g_mask_mode;   // 0 = uint8/bool, 1 = int32, 2 = float32

// ---------------------------------------------------------------------------
// f32x2 packed-FMA helpers (sm_100+ FFMA2 — only reachable via PTX)
// ---------------------------------------------------------------------------
__device__ __forceinline__ void ffma2(uint64_t& d, uint64_t a, uint64_t b) {
    asm("fma.rn.f32x2 %0, %1, %2, %0;" : "+l"(d) : "l"(a), "l"(b));
}
__device__ __forceinline__ uint64_t dupf(float x) {
    uint64_t r; asm("mov.b64 %0, {%1, %1};" : "=l"(r) : "f"(x)); return r;
}
__device__ __forceinline__ float2 unpack2(uint64_t v) {
    float2 f; asm("mov.b64 {%0, %1}, %2;" : "=f"(f.x), "=f"(f.y) : "l"(v)); return f;
}

// ---------------------------------------------------------------------------
// Mask dtype probe (deterministic). float32 bool words in {0, 0x3F800000};
// int32 bool in {0,1}; packed uint8 bool -> words with multiple 0/1 bytes.
// ---------------------------------------------------------------------------
__global__ void detect_mask_kernel(const void* __restrict__ mask) {
    __shared__ int sawFloat, sawOther;
    if (threadIdx.x == 0) { sawFloat = 0; sawOther = 0; }
    __syncthreads();
    const unsigned int* w = (const unsigned int*)mask;
    int lf = 0, lo = 0;
    for (int i = threadIdx.x; i < 2048; i += blockDim.x) {
        unsigned int x = w[i];
        if (x == 0x3F800000u) lf = 1;
        else if (x > 1u) lo = 1;
    }
    if (lf) atomicOr(&sawFloat, 1);
    if (lo) atomicOr(&sawOther, 1);
    __syncthreads();
    if (threadIdx.x == 0) g_mask_mode = sawFloat ? 2 : (sawOther ? 0 : 1);
}

__device__ __forceinline__ bool read_mask(const void* m, size_t idx, int mode) {
    if (mode == 0) return ((const unsigned char*)m)[idx] != 0;
    if (mode == 1) return ((const int*)m)[idx] != 0;
    return ((const float*)m)[idx] != 0.0f;
}

// ---------------------------------------------------------------------------
// Kernel 1: fused Q/K/V projections. Y = X @ W^T + bias -> [b][h][s][hd].
// NT GEMM, M=8192, N=768, K=768. Tile 128x128x16, 256 threads.
// FFMA2: accumulators paired along M (As rows contiguous), B duplicated.
// ---------------------------------------------------------------------------
__global__ __launch_bounds__(256, 2) void proj_kernel(
    const float* __restrict__ Xq, const float* __restrict__ Xk, const float* __restrict__ Xv,
    const float* __restrict__ Wq, const float* __restrict__ Wk, const float* __restrict__ Wv,
    const float* __restrict__ bq, const float* __restrict__ bk, const float* __restrict__ bv)
{
    const int z = blockIdx.z;
    const float* X    = (z == 0) ? Xq : (z == 1) ? Xk : Xv;
    const float* W    = (z == 0) ? Wq : (z == 1) ? Wk : Wv;
    const float* bias = (z == 0) ? bq : (z == 1) ? bk : bv;
    float* out        = (z == 0) ? g_q : (z == 1) ? g_k : g_v;

    __shared__ __align__(16) float As[16][136];   // [k][m], padded (544B rows, 16B-mult)
    __shared__ __align__(16) float Bs[16][136];   // [k][n], padded

    const int tid = threadIdx.x;
    const int tx = tid & 15;        // n microtile group
    const int ty = tid >> 4;        // m microtile group
    const int m0 = blockIdx.y * 128;
    const int n0 = blockIdx.x * 128;

    uint64_t acc2[4][8];            // pairs along M: rows (2*ih, 2*ih+1), cols j
#pragma unroll
    for (int i = 0; i < 4; i++)
#pragma unroll
        for (int j = 0; j < 8; j++) acc2[i][j] = 0ull;

    const int lrow = tid >> 1;          // 0..127
    const int lk   = (tid & 1) * 8;     // 0 or 8
    const float* Arow = X + (size_t)(m0 + lrow) * PD + lk;
    const float* Brow = W + (size_t)(n0 + lrow) * PD + lk;

    float4 pa0 = *(const float4*)(Arow);
    float4 pa1 = *(const float4*)(Arow + 4);
    float4 pb0 = *(const float4*)(Brow);
    float4 pb1 = *(const float4*)(Brow + 4);

    for (int k0 = 0; k0 < PD; k0 += 16) {
        __syncthreads();
        As[lk + 0][lrow] = pa0.x; As[lk + 1][lrow] = pa0.y;
        As[lk + 2][lrow] = pa0.z; As[lk + 3][lrow] = pa0.w;
        As[lk + 4][lrow] = pa1.x; As[lk + 5][lrow] = pa1.y;
        As[lk + 6][lrow] = pa1.z; As[lk + 7][lrow] = pa1.w;
        Bs[lk + 0][lrow] = pb0.x; Bs[lk + 1][lrow] = pb0.y;
        Bs[lk + 2][lrow] = pb0.z; Bs[lk + 3][lrow] = pb0.w;
        Bs[lk + 4][lrow] = pb1.x; Bs[lk + 5][lrow] = pb1.y;
        Bs[lk + 6][lrow] = pb1.z; Bs[lk + 7][lrow] = pb1.w;
        __syncthreads();
        if (k0 + 16 < PD) {  // prefetch next K-slab into registers
            pa0 = *(const float4*)(Arow + k0 + 16);
            pa1 = *(const float4*)(Arow + k0 + 20);
            pb0 = *(const float4*)(Brow + k0 + 16);
            pb1 = *(const float4*)(Brow + k0 + 20);
        }
#pragma unroll
        for (int kk = 0; kk < 16; kk++) {
            // A pairs come free from LDS.128 (even-aligned reg pairs)
            ulonglong2 av0 = *(const ulonglong2*)&As[kk][ty * 8];      // (m0,m1),(m2,m3)
            ulonglong2 av1 = *(const ulonglong2*)&As[kk][ty * 8 + 4];  // (m4,m5),(m6,m7)
            float bb[8];
            *(float4*)&bb[0] = *(const float4*)&Bs[kk][tx * 8];
            *(float4*)&bb[4] = *(const float4*)&Bs[kk][tx * 8 + 4];
#pragma unroll
            for (int j = 0; j < 8; j++) {
                const uint64_t db = dupf(bb[j]);
                ffma2(acc2[0][j], av0.x, db);
                ffma2(acc2[1][j], av0.y, db);
                ffma2(acc2[2][j], av1.x, db);
                ffma2(acc2[3][j], av1.y, db);
            }
        }
    }

    // epilogue: scatter to [b][h][s][hd] (+bias)
    const int ncol0 = n0 + tx * 8;
    const int h  = ncol0 >> 6;          // 8-col microtile never crosses a head
    const int hd = ncol0 & 63;
    float bi[8];
#pragma unroll
    for (int j = 0; j < 8; j++) bi[j] = bias[ncol0 + j];
#pragma unroll
    for (int ih = 0; ih < 4; ih++) {
        float r0[8], r1[8];
#pragma unroll
        for (int j = 0; j < 8; j++) {
            const float2 u = unpack2(acc2[ih][j]);
            r0[j] = u.x + bi[j];
            r1[j] = u.y + bi[j];
        }
#pragma unroll
        for (int rr = 0; rr < 2; rr++) {
            const int m = m0 + ty * 8 + ih * 2 + rr;
            const int b = m >> 10;
            const int s = m & 1023;
            float* dst = out + (((size_t)(b * PH + h)) * PS + s) * PHD + hd;
            const float* rsrc = rr ? r1 : r0;
            float4 o0, o1;
            o0.x = rsrc[0]; o0.y = rsrc[1]; o0.z = rsrc[2]; o0.w = rsrc[3];
            o1.x = rsrc[4]; o1.y = rsrc[5]; o1.z = rsrc[6]; o1.w = rsrc[7];
            *(float4*)(dst)     = o0;
            *(float4*)(dst + 4) = o1;
        }
    }
}

// ---------------------------------------------------------------------------
// Kernel 2: per (b, 16-row q-tile): rel-softmax + mask ONCE, then loop heads:
// S = QK^T/8 (masked), softmax, combine, write prob_attn.
// smem layout (bytes):
//   relp  [16][1024] f32   @ 0        (65536)
//   sbuf  [16][1024] f32   @ 65536    (65536)
//   kts   [128][65]  f32   @ 131072   (33280)
//   qtsT  [64][16]   f32   @ 164352   (4096)
//   msk   [16][1024] u8    @ 168448   (16384)
// ---------------------------------------------------------------------------
constexpr int QT = 16, KC = 128;
constexpr size_t K2_SMEM = 184832;

__global__ void attn_scores_kernel(const float* __restrict__ rel,
                                   const void* __restrict__ mask,
                                   const float* __restrict__ l1p,
                                   float* __restrict__ prob)
{
    extern __shared__ __align__(16) unsigned char smem[];
    float* relp = (float*)smem;
    float* sbuf = (float*)(smem + 65536);
    float* kts  = (float*)(smem + 131072);
    float* qtsT = (float*)(smem + 164352);
    unsigned char* msk = smem + 168448;

    const int tid  = threadIdx.x;
    const int lane = tid & 31;
    const int warp = tid >> 5;
    const int b  = blockIdx.y;
    const int q0 = blockIdx.x * QT;
    const int mmode = g_mask_mode;
    const float l1 = *l1p;
    const float w0 = 1.0f - l1;

    // Phase 0: mask tile + rel_attn tile
#pragma unroll
    for (int rr = 0; rr < 2; rr++) {
        const int r = warp + rr * 8;
        const size_t rbase = ((size_t)b * PS + q0 + r) * PS;
        float mx = -3.0e38f;
        for (int c = lane; c < PS; c += 32) {
            const bool m = read_mask(mask, rbase + c, mmode);
            msk[r * PS + c] = m ? 1 : 0;
            const float v = rel[rbase + c];
            const float relm = m ? v : 0.0f;
            const float logit = (relm == 0.0f) ? -10000.0f : relm;
            relp[r * PS + c] = logit;
            mx = fmaxf(mx, logit);
        }
#pragma unroll
        for (int o = 16; o; o >>= 1) mx = fmaxf(mx, __shfl_xor_sync(0xffffffffu, mx, o));
        float sum = 0.0f;
        for (int c = lane; c < PS; c += 32) {
            const float e = __expf(relp[r * PS + c] - mx);
            relp[r * PS + c] = e;
            sum += e;
        }
#pragma unroll
        for (int o = 16; o; o >>= 1) sum += __shfl_xor_sync(0xffffffffu, sum, o);
        const float inv = 1.0f / sum;
        for (int c = lane; c < PS; c += 32) relp[r * PS + c] *= inv;
    }
    __syncthreads();

    for (int h = 0; h < PH; h++) {
        // load Q tile, transposed to [d][q]
        const size_t qbase = (((size_t)b * PH + h) * PS + q0) * PHD;
#pragma unroll
        for (int it = 0; it < 4; it++) {
            const int i = tid + it * 256;
            const int r = i >> 6, hd = i & 63;
            qtsT[hd * QT + r] = g_q[qbase + (size_t)r * PHD + hd];
        }
        const size_t kbase = (((size_t)b * PH + h) * PS) * PHD;

        for (int kc0 = 0; kc0 < PS; kc0 += KC) {
            __syncthreads();
            const float4* src = (const float4*)(g_k + kbase + (size_t)kc0 * PHD);
#pragma unroll
            for (int it = 0; it < 8; it++) {
                const int i4 = tid + it * 256;            // 0..2047
                const int kr = i4 >> 4, hd0 = (i4 & 15) << 2;
                const float4 vv = src[(size_t)kr * 16 + (hd0 >> 2)];
                float* drow = kts + kr * 65 + hd0;
                drow[0] = vv.x; drow[1] = vv.y; drow[2] = vv.z; drow[3] = vv.w;
            }
            __syncthreads();
            // 16 x 128 scores: 4 qg x 64 kg; micro 4q x 2k via FFMA2 (pairs over q)
            const int kg = tid & 63, qg = tid >> 6;
            uint64_t acc2[2][2];
            acc2[0][0] = 0ull; acc2[0][1] = 0ull;
            acc2[1][0] = 0ull; acc2[1][1] = 0ull;
            const float* kr0 = kts + (kg * 2) * 65;
            const float* kr1 = kr0 + 65;
            const float* qcol = qtsT + qg * 4;
#pragma unroll 16
            for (int d = 0; d < PHD; d++) {
                const ulonglong2 qv = *(const ulonglong2*)(qcol + d * QT); // (q0,q1),(q2,q3)
                const uint64_t dk0 = dupf(kr0[d]);
                const uint64_t dk1 = dupf(kr1[d]);
                ffma2(acc2[0][0], qv.x, dk0);
                ffma2(acc2[0][1], qv.x, dk1);
                ffma2(acc2[1][0], qv.y, dk0);
                ffma2(acc2[1][1], qv.y, dk1);
            }
#pragma unroll
            for (int p = 0; p < 2; p++) {
                const float2 u0 = unpack2(acc2[p][0]);   // k col +0, rows (2p, 2p+1)
                const float2 u1 = unpack2(acc2[p][1]);   // k col +1
                const int q = qg * 4 + p * 2;
                const int kcol = kc0 + kg * 2;
                sbuf[q * PS + kcol]           = msk[q * PS + kcol]           ? -1.0e9f : u0.x * 0.125f;
                sbuf[q * PS + kcol + 1]       = msk[q * PS + kcol + 1]       ? -1.0e9f : u1.x * 0.125f;
                sbuf[(q + 1) * PS + kcol]     = msk[(q + 1) * PS + kcol]     ? -1.0e9f : u0.y * 0.125f;
                sbuf[(q + 1) * PS + kcol + 1] = msk[(q + 1) * PS + kcol + 1] ? -1.0e9f : u1.y * 0.125f;
            }
        }
        __syncthreads();
        // softmax + combine + write prob_attn
        const size_t pbase = (((size_t)b * PH + h) * PS + q0) * PS;
#pragma unroll
        for (int rr = 0; rr < 2; rr++) {
            const int r = warp + rr * 8;
            float mx = -3.0e38f;
            for (int c = lane; c < PS; c += 32) mx = fmaxf(mx, sbuf[r * PS + c]);
#pragma unroll
            for (int o = 16; o; o >>= 1) mx = fmaxf(mx, __shfl_xor_sync(0xffffffffu, mx, o));
            float sum = 0.0f;
            for (int c = lane; c < PS; c += 32) {
                const float e = __expf(sbuf[r * PS + c] - mx);
                sbuf[r * PS + c] = e;
                sum += e;
            }
#pragma unroll
            for (int o = 16; o; o >>= 1) sum += __shfl_xor_sync(0xffffffffu, sum, o);
            const float inv = 1.0f / sum;
            for (int c = lane; c < PS; c += 32)
                prob[pbase + (size_t)r * PS + c] = w0 * (sbuf[r * PS + c] * inv)
                                                 + l1 * relp[r * PS + c];
        }
        __syncthreads();
    }
}

// ---------------------------------------------------------------------------
// Kernel 3: out = prob @ V per (b,h). M=1024, N=64, K=1024. Tile 128x64x32,
// 256 threads. FFMA2: pairs along Q (pt rows contiguous), V duplicated.
// ---------------------------------------------------------------------------
__global__ __launch_bounds__(256, 2) void pv_kernel(const float* __restrict__ prob,
                                                    float* __restrict__ outp)
{
    __shared__ __align__(16) float pt[32][136];   // [k][q] transposed, padded
    __shared__ __align__(16) float vt[32][64];    // [k][n]

    const int bh = blockIdx.y;
    const int b = bh / PH, h = bh % PH;
    const int q0 = blockIdx.x * 128;
    const int tid = threadIdx.x;
    const int ng = tid & 15, qg = tid >> 4;

    uint64_t acc2[4][4];   // pairs along q: rows (2ip, 2ip+1), cols j
#pragma unroll
    for (int i = 0; i < 4; i++)
#pragma unroll
        for (int j = 0; j < 4; j++) acc2[i][j] = 0ull;

    const size_t pbase = ((size_t)bh * PS + q0) * PS;
    const size_t vbase = (size_t)bh * PS * PHD;

    for (int kc0 = 0; kc0 < PS; kc0 += 32) {
        __syncthreads();
#pragma unroll
        for (int it = 0; it < 4; it++) {            // pt: 128q x 32k
            const int i4 = tid + it * 256;          // 0..1023
            const int q = i4 >> 3, kq = (i4 & 7) << 2;
            const float4 v = *(const float4*)(prob + pbase + (size_t)q * PS + kc0 + kq);
            pt[kq + 0][q] = v.x; pt[kq + 1][q] = v.y;
            pt[kq + 2][q] = v.z; pt[kq + 3][q] = v.w;
        }
#pragma unroll
        for (int it = 0; it < 2; it++) {            // vt: 32k x 64n
            const int i4 = tid + it * 256;          // 0..511
            const int kr = i4 >> 4, n = (i4 & 15) << 2;
            *(float4*)&vt[kr][n] = *(const float4*)(g_v + vbase + (size_t)(kc0 + kr) * PHD + n);
        }
        __syncthreads();
#pragma unroll 8
        for (int kk = 0; kk < 32; kk++) {
            const ulonglong2 p01 = *(const ulonglong2*)&pt[kk][qg * 8];      // (p0,p1),(p2,p3)
            const ulonglong2 p23 = *(const ulonglong2*)&pt[kk][qg * 8 + 4];  // (p4,p5),(p6,p7)
            float vv[4];
            *(float4*)&vv[0] = *(const float4*)&vt[kk][ng * 4];
#pragma unroll
            for (int j = 0; j < 4; j++) {
                const uint64_t dv = dupf(vv[j]);
                ffma2(acc2[0][j], p01.x, dv);
                ffma2(acc2[1][j], p01.y, dv);
                ffma2(acc2[2][j], p23.x, dv);
                ffma2(acc2[3][j], p23.y, dv);
            }
        }
    }
#pragma unroll
    for (int ip = 0; ip < 4; ip++) {
        float o0[4], o1[4];
#pragma unroll
        for (int j = 0; j < 4; j++) {
            const float2 u = unpack2(acc2[ip][j]);
            o0[j] = u.x; o1[j] = u.y;
        }
        const int q = q0 + qg * 8 + ip * 2;
        *(float4*)&outp[((size_t)b * PS + q) * PD + h * PHD + ng * 4]       = *(float4*)o0;
        *(float4*)&outp[((size_t)b * PS + q + 1) * PD + h * PHD + ng * 4]   = *(float4*)o1;
    }
}

// ---------------------------------------------------------------------------
extern "C" void kernel_launch(void* const* d_in, const int* in_sizes, int n_in,
                              void* d_out, int out_size) {
    const float* query = (const float*)d_in[0];
    const float* key   = (const float*)d_in[1];
    const float* value = (const float*)d_in[2];
    const float* rel   = (const float*)d_in[3];
    const void*  mask  = d_in[4];
    const float* l1    = (const float*)d_in[5];
    const float* Wq    = (const float*)d_in[6];
    const float* bq    = (const float*)d_in[7];
    const float* Wk    = (const float*)d_in[8];
    const float* bk    = (const float*)d_in[9];
    const float* Wv    = (const float*)d_in[10];
    const float* bv    = (const float*)d_in[11];

    float* outp = (float*)d_out;
    float* prob = outp + OUT_ELEMS;

    detect_mask_kernel<<<1, 256>>>(mask);

    dim3 g1(PD / 128, (PB * PS) / 128, 3);     // (6, 64, 3)
    proj_kernel<<<g1, 256>>>(query, key, value, Wq, Wk, Wv, bq, bk, bv);

    cudaFuncSetAttribute(attn_scores_kernel,
                         cudaFuncAttributeMaxDynamicSharedMemorySize, (int)K2_SMEM);
    dim3 g2(PS / QT, PB);                      // (64, 8)
    attn_scores_kernel<<<g2, 256, K2_SMEM>>>(rel, mask, l1, prob);

    dim3 g3(PS / 128, PB * PH);                // (8, 96)
    pv_kernel<<<g3, 256>>>(prob, outp);
}

// round 7
// speedup vs baseline: 1.2109x; 1.1680x over previous
#include <cuda_runtime.h>
#include <cuda_bf16.h>
#include <cstdint>
#include <cstddef>

// Problem constants
constexpr int PB = 8, PS = 1024, PD = 768, PH = 12, PHD = 64;
constexpr size_t QKV_ELEMS = (size_t)PB * PH * PS * PHD;        // 6,291,456
constexpr size_t OUT_ELEMS = (size_t)PB * PS * PD;              // 6,291,456
constexpr size_t XE = (size_t)PB * PS * PD;                     // 6,291,456 per matrix
constexpr size_t WE = (size_t)PD * PD;                          // 589,824 per matrix

// Scratch (no allocations allowed -> __device__ globals)
__device__ float g_q[QKV_ELEMS];
__device__ float g_k[QKV_ELEMS];
__device__ float g_v[QKV_ELEMS];
__device__ __nv_bfloat16 g_xhi[3 * XE];
__device__ __nv_bfloat16 g_xlo[3 * XE];
__device__ __nv_bfloat16 g_whi[3 * WE];
__device__ __nv_bfloat16 g_wlo[3 * WE];
__device__ int   g_mask_mode;   // 0 = uint8/bool, 1 = int32, 2 = float32

// ---------------------------------------------------------------------------
// f32x2 packed-FMA helpers (scores/pv)
// ---------------------------------------------------------------------------
__device__ __forceinline__ void ffma2(uint64_t& d, uint64_t a, uint64_t b) {
    asm("fma.rn.f32x2 %0, %1, %2, %0;" : "+l"(d) : "l"(a), "l"(b));
}
__device__ __forceinline__ uint64_t dupf(float x) {
    uint64_t r; asm("mov.b64 %0, {%1, %1};" : "=l"(r) : "f"(x)); return r;
}
__device__ __forceinline__ float2 unpack2(uint64_t v) {
    float2 f; asm("mov.b64 {%0, %1}, %2;" : "=f"(f.x), "=f"(f.y) : "l"(v)); return f;
}

// ---------------------------------------------------------------------------
// Tensor-core helpers (portable sm_80+ path: ldmatrix + mma.sync bf16)
// ---------------------------------------------------------------------------
__device__ __forceinline__ uint32_t smem_to_u32(const void* p) {
    uint32_t a;
    asm("{ .reg .u64 t; cvta.to.shared.u64 t, %1; cvt.u32.u64 %0, t; }" : "=r"(a) : "l"(p));
    return a;
}
__device__ __forceinline__ void ldmx4(uint32_t* r, uint32_t addr) {
    asm volatile("ldmatrix.sync.aligned.m8n8.x4.shared.b16 {%0,%1,%2,%3}, [%4];"
        : "=r"(r[0]), "=r"(r[1]), "=r"(r[2]), "=r"(r[3]) : "r"(addr));
}
__device__ __forceinline__ void mma16816(float* c, const uint32_t* a, uint32_t b0, uint32_t b1) {
    asm volatile("mma.sync.aligned.m16n8k16.row.col.f32.bf16.bf16.f32 "
        "{%0,%1,%2,%3}, {%4,%5,%6,%7}, {%8,%9}, {%0,%1,%2,%3};"
        : "+f"(c[0]), "+f"(c[1]), "+f"(c[2]), "+f"(c[3])
        : "r"(a[0]), "r"(a[1]), "r"(a[2]), "r"(a[3]), "r"(b0), "r"(b1));
}
#define SWZ128(off) ((off) ^ (((off) >> 3) & 0x70))

// ---------------------------------------------------------------------------
// Mask dtype probe (deterministic)
// ---------------------------------------------------------------------------
__global__ void detect_mask_kernel(const void* __restrict__ mask) {
    __shared__ int sawFloat, sawOther;
    if (threadIdx.x == 0) { sawFloat = 0; sawOther = 0; }
    __syncthreads();
    const unsigned int* w = (const unsigned int*)mask;
    int lf = 0, lo = 0;
    for (int i = threadIdx.x; i < 2048; i += blockDim.x) {
        unsigned int x = w[i];
        if (x == 0x3F800000u) lf = 1;
        else if (x > 1u) lo = 1;
    }
    if (lf) atomicOr(&sawFloat, 1);
    if (lo) atomicOr(&sawOther, 1);
    __syncthreads();
    if (threadIdx.x == 0) g_mask_mode = sawFloat ? 2 : (sawOther ? 0 : 1);
}

__device__ __forceinline__ bool read_mask(const void* m, size_t idx, int mode) {
    if (mode == 0) return ((const unsigned char*)m)[idx] != 0;
    if (mode == 1) return ((const int*)m)[idx] != 0;
    return ((const float*)m)[idx] != 0.0f;
}

// ---------------------------------------------------------------------------
// Conversion kernels: fp32 -> (bf16 hi, bf16 lo) split
// ---------------------------------------------------------------------------
__global__ void conv_x_kernel(const float* __restrict__ q, const float* __restrict__ k,
                              const float* __restrict__ v) {
    const int z = blockIdx.y;
    const float* src = (z == 0) ? q : (z == 1) ? k : v;
    __nv_bfloat16* hi = g_xhi + (size_t)z * XE;
    __nv_bfloat16* lo = g_xlo + (size_t)z * XE;
    const size_t i2 = ((size_t)blockIdx.x * blockDim.x + threadIdx.x) * 2;
    if (i2 + 1 >= XE) return;
    const float2 s = *(const float2*)(src + i2);
    const __nv_bfloat16 h0 = __float2bfloat16_rn(s.x);
    const __nv_bfloat16 h1 = __float2bfloat16_rn(s.y);
    const __nv_bfloat16 l0 = __float2bfloat16_rn(s.x - __bfloat162float(h0));
    const __nv_bfloat16 l1 = __float2bfloat16_rn(s.y - __bfloat162float(h1));
    __nv_bfloat162 hp; hp.x = h0; hp.y = h1;
    __nv_bfloat162 lp; lp.x = l0; lp.y = l1;
    *(__nv_bfloat162*)(hi + i2) = hp;
    *(__nv_bfloat162*)(lo + i2) = lp;
}

__global__ void conv_w_kernel(const float* __restrict__ wq, const float* __restrict__ wk,
                              const float* __restrict__ wv) {
    const int z = blockIdx.y;
    const float* src = (z == 0) ? wq : (z == 1) ? wk : wv;
    __nv_bfloat16* hi = g_whi + (size_t)z * WE;
    __nv_bfloat16* lo = g_wlo + (size_t)z * WE;
    const size_t i2 = ((size_t)blockIdx.x * blockDim.x + threadIdx.x) * 2;
    if (i2 + 1 >= WE) return;
    const float2 s = *(const float2*)(src + i2);
    const __nv_bfloat16 h0 = __float2bfloat16_rn(s.x);
    const __nv_bfloat16 h1 = __float2bfloat16_rn(s.y);
    const __nv_bfloat16 l0 = __float2bfloat16_rn(s.x - __bfloat162float(h0));
    const __nv_bfloat16 l1 = __float2bfloat16_rn(s.y - __bfloat162float(h1));
    __nv_bfloat162 hp; hp.x = h0; hp.y = h1;
    __nv_bfloat162 lp; lp.x = l0; lp.y = l1;
    *(__nv_bfloat162*)(hi + i2) = hp;
    *(__nv_bfloat162*)(lo + i2) = lp;
}

// ---------------------------------------------------------------------------
// Kernel 1: HMMA bf16-split projection GEMM.
// Y[8192,768] = X @ W^T + b per matrix z. CTA tile 128x128, 8 warps (64x32
// warp tiles), K-slabs of 64 (=128B SW128 rows). 3 mma terms per fragment:
// Ahi*Bhi + Alo*Bhi + Ahi*Blo, fp32 accumulators.
// smem: Ahi,Alo,Bhi,Blo each 128 rows x 64 bf16 (16KB), SW128-swizzled.
// ---------------------------------------------------------------------------
constexpr int PROJ_SMEM = 4 * 16384;   // 64KB dynamic

__device__ __forceinline__ void load_slab_part(const __nv_bfloat16* __restrict__ src,
                                               int row0, int k0, char* dst, int tid) {
#pragma unroll
    for (int it = 0; it < 4; it++) {
        const int c = tid + it * 256;          // 0..1023 16B-chunks
        const int r = c >> 3;                  // 0..127
        const int e8 = (c & 7) * 8;            // bf16 element offset in row (0..56)
        const uint4 v = *(const uint4*)(src + (size_t)(row0 + r) * PD + k0 + e8);
        *(uint4*)(dst + SWZ128(r * 128 + e8 * 2)) = v;
    }
}

__global__ __launch_bounds__(256, 2)
void proj_mma_kernel(const float* __restrict__ bq, const float* __restrict__ bk,
                     const float* __restrict__ bv)
{
    extern __shared__ char sm[];
    __shared__ float bias_s[128];

    const int tid  = threadIdx.x;
    const int warp = tid >> 5;
    const int lane = tid & 31;
    const int wm = warp >> 2;      // 0..1 -> 64 rows each
    const int wn = warp & 3;       // 0..3 -> 32 cols each
    const int z  = blockIdx.z;
    const int n0 = blockIdx.x * 128;
    const int m0 = blockIdx.y * 128;

    const __nv_bfloat16* xhi = g_xhi + (size_t)z * XE;
    const __nv_bfloat16* xlo = g_xlo + (size_t)z * XE;
    const __nv_bfloat16* whi = g_whi + (size_t)z * WE;
    const __nv_bfloat16* wlo = g_wlo + (size_t)z * WE;
    const float* bias = (z == 0) ? bq : (z == 1) ? bk : bv;
    float* outp       = (z == 0) ? g_q : (z == 1) ? g_k : g_v;

    if (tid < 128) bias_s[tid] = bias[n0 + tid];

    char* Ahi_s = sm;
    char* Alo_s = sm + 16384;
    char* Bhi_s = sm + 32768;
    char* Blo_s = sm + 49152;
    const uint32_t uAhi = smem_to_u32(Ahi_s);
    const uint32_t uAlo = smem_to_u32(Alo_s);
    const uint32_t uBhi = smem_to_u32(Bhi_s);
    const uint32_t uBlo = smem_to_u32(Blo_s);

    float acc[4][4][4];   // [m16 tile][n8 tile][c-frag]
#pragma unroll
    for (int i = 0; i < 4; i++)
#pragma unroll
        for (int j = 0; j < 4; j++)
#pragma unroll
            for (int c = 0; c < 4; c++) acc[i][j][c] = 0.0f;

    // ldmatrix lane addressing: row = lane&15 within tile, col byte = (lane>>4)*16
    const int lrow   = lane & 15;
    const int lcolb  = (lane >> 4) * 16;

    for (int s = 0; s < 12; s++) {
        __syncthreads();
        const int k0 = s * 64;
        load_slab_part(xhi, m0, k0, Ahi_s, tid);
        load_slab_part(xlo, m0, k0, Alo_s, tid);
        load_slab_part(whi, n0, k0, Bhi_s, tid);
        load_slab_part(wlo, n0, k0, Blo_s, tid);
        __syncthreads();
#pragma unroll
        for (int ks = 0; ks < 4; ks++) {
            const int kb = ks * 32 + lcolb;     // byte offset within 128B row
            // B fragments: 2x (n16-tile) ldmatrix.x4 each for hi and lo.
            // regs: r0=(n0-7,k0-7) r1=(n8-15,k0-7) r2=(n0-7,k8-15) r3=(n8-15,k8-15)
            uint32_t bhi[2][4], blo[2][4];
#pragma unroll
            for (int nt2 = 0; nt2 < 2; nt2++) {
                const int brow = wn * 32 + nt2 * 16 + lrow;
                ldmx4(bhi[nt2], uBhi + SWZ128(brow * 128 + kb));
                ldmx4(blo[nt2], uBlo + SWZ128(brow * 128 + kb));
            }
#pragma unroll
            for (int mt = 0; mt < 4; mt++) {
                const int arow = wm * 64 + mt * 16 + lrow;
                uint32_t a[4];
                ldmx4(a, uAhi + SWZ128(arow * 128 + kb));       // Ahi
#pragma unroll
                for (int nt2 = 0; nt2 < 2; nt2++)
#pragma unroll
                    for (int j = 0; j < 2; j++) {
                        mma16816(acc[mt][nt2 * 2 + j], a, bhi[nt2][j], bhi[nt2][2 + j]);
                        mma16816(acc[mt][nt2 * 2 + j], a, blo[nt2][j], blo[nt2][2 + j]);
                    }
                ldmx4(a, uAlo + SWZ128(arow * 128 + kb));       // Alo
#pragma unroll
                for (int nt2 = 0; nt2 < 2; nt2++)
#pragma unroll
                    for (int j = 0; j < 2; j++)
                        mma16816(acc[mt][nt2 * 2 + j], a, bhi[nt2][j], bhi[nt2][2 + j]);
            }
        }
    }

    // Epilogue: c0,c1 -> (m=g, n=tg2, tg2+1); c2,c3 -> (m=g+8, same n)
    const int g   = lane >> 2;
    const int tg2 = (lane & 3) * 2;
#pragma unroll
    for (int mt = 0; mt < 4; mt++) {
#pragma unroll
        for (int nt = 0; nt < 4; nt++) {
            const int nc = wn * 32 + nt * 8 + tg2;      // 0..127
            const int n = n0 + nc;
            const int h = n >> 6, hd = n & 63;
            const int m = m0 + wm * 64 + mt * 16 + g;
            const int b = m >> 10, sq = m & 1023;
            float2 v0, v1;
            v0.x = acc[mt][nt][0] + bias_s[nc];
            v0.y = acc[mt][nt][1] + bias_s[nc + 1];
            v1.x = acc[mt][nt][2] + bias_s[nc];
            v1.y = acc[mt][nt][3] + bias_s[nc + 1];
            *(float2*)(outp + (((size_t)(b * PH + h)) * PS + sq) * PHD + hd)       = v0;
            *(float2*)(outp + (((size_t)(b * PH + h)) * PS + sq + 8) * PHD + hd)   = v1;
        }
    }
}

// ---------------------------------------------------------------------------
// Kernel 2: per (b, 16-row q-tile): rel-softmax + mask ONCE, then loop heads:
// S = QK^T/8 (masked), softmax, combine, write prob_attn. (unchanged)
// ---------------------------------------------------------------------------
constexpr int QT = 16, KC = 128;
constexpr size_t K2_SMEM = 184832;

__global__ void attn_scores_kernel(const float* __restrict__ rel,
                                   const void* __restrict__ mask,
                                   const float* __restrict__ l1p,
                                   float* __restrict__ prob)
{
    extern __shared__ __align__(16) unsigned char smem[];
    float* relp = (float*)smem;
    float* sbuf = (float*)(smem + 65536);
    float* kts  = (float*)(smem + 131072);
    float* qtsT = (float*)(smem + 164352);
    unsigned char* msk = smem + 168448;

    const int tid  = threadIdx.x;
    const int lane = tid & 31;
    const int warp = tid >> 5;
    const int b  = blockIdx.y;
    const int q0 = blockIdx.x * QT;
    const int mmode = g_mask_mode;
    const float l1 = *l1p;
    const float w0 = 1.0f - l1;

#pragma unroll
    for (int rr = 0; rr < 2; rr++) {
        const int r = warp + rr * 8;
        const size_t rbase = ((size_t)b * PS + q0 + r) * PS;
        float mx = -3.0e38f;
        for (int c = lane; c < PS; c += 32) {
            const bool m = read_mask(mask, rbase + c, mmode);
            msk[r * PS + c] = m ? 1 : 0;
            const float v = rel[rbase + c];
            const float relm = m ? v : 0.0f;
            const float logit = (relm == 0.0f) ? -10000.0f : relm;
            relp[r * PS + c] = logit;
            mx = fmaxf(mx, logit);
        }
#pragma unroll
        for (int o = 16; o; o >>= 1) mx = fmaxf(mx, __shfl_xor_sync(0xffffffffu, mx, o));
        float sum = 0.0f;
        for (int c = lane; c < PS; c += 32) {
            const float e = __expf(relp[r * PS + c] - mx);
            relp[r * PS + c] = e;
            sum += e;
        }
#pragma unroll
        for (int o = 16; o; o >>= 1) sum += __shfl_xor_sync(0xffffffffu, sum, o);
        const float inv = 1.0f / sum;
        for (int c = lane; c < PS; c += 32) relp[r * PS + c] *= inv;
    }
    __syncthreads();

    for (int h = 0; h < PH; h++) {
        const size_t qbase = (((size_t)b * PH + h) * PS + q0) * PHD;
#pragma unroll
        for (int it = 0; it < 4; it++) {
            const int i = tid + it * 256;
            const int r = i >> 6, hd = i & 63;
            qtsT[hd * QT + r] = g_q[qbase + (size_t)r * PHD + hd];
        }
        const size_t kbase = (((size_t)b * PH + h) * PS) * PHD;

        for (int kc0 = 0; kc0 < PS; kc0 += KC) {
            __syncthreads();
            const float4* src = (const float4*)(g_k + kbase + (size_t)kc0 * PHD);
#pragma unroll
            for (int it = 0; it < 8; it++) {
                const int i4 = tid + it * 256;            // 0..2047
                const int kr = i4 >> 4, hd0 = (i4 & 15) << 2;
                const float4 vv = src[(size_t)kr * 16 + (hd0 >> 2)];
                float* drow = kts + kr * 65 + hd0;
                drow[0] = vv.x; drow[1] = vv.y; drow[2] = vv.z; drow[3] = vv.w;
            }
            __syncthreads();
            const int kg = tid & 63, qg = tid >> 6;
            uint64_t acc2[2][2];
            acc2[0][0] = 0ull; acc2[0][1] = 0ull;
            acc2[1][0] = 0ull; acc2[1][1] = 0ull;
            const float* kr0 = kts + (kg * 2) * 65;
            const float* kr1 = kr0 + 65;
            const float* qcol = qtsT + qg * 4;
#pragma unroll 16
            for (int d = 0; d < PHD; d++) {
                const ulonglong2 qv = *(const ulonglong2*)(qcol + d * QT);
                const uint64_t dk0 = dupf(kr0[d]);
                const uint64_t dk1 = dupf(kr1[d]);
                ffma2(acc2[0][0], qv.x, dk0);
                ffma2(acc2[0][1], qv.x, dk1);
                ffma2(acc2[1][0], qv.y, dk0);
                ffma2(acc2[1][1], qv.y, dk1);
            }
#pragma unroll
            for (int p = 0; p < 2; p++) {
                const float2 u0 = unpack2(acc2[p][0]);
                const float2 u1 = unpack2(acc2[p][1]);
                const int q = qg * 4 + p * 2;
                const int kcol = kc0 + kg * 2;
                sbuf[q * PS + kcol]           = msk[q * PS + kcol]           ? -1.0e9f : u0.x * 0.125f;
                sbuf[q * PS + kcol + 1]       = msk[q * PS + kcol + 1]       ? -1.0e9f : u1.x * 0.125f;
                sbuf[(q + 1) * PS + kcol]     = msk[(q + 1) * PS + kcol]     ? -1.0e9f : u0.y * 0.125f;
                sbuf[(q + 1) * PS + kcol + 1] = msk[(q + 1) * PS + kcol + 1] ? -1.0e9f : u1.y * 0.125f;
            }
        }
        __syncthreads();
        const size_t pbase = (((size_t)b * PH + h) * PS + q0) * PS;
#pragma unroll
        for (int rr = 0; rr < 2; rr++) {
            const int r = warp + rr * 8;
            float mx = -3.0e38f;
            for (int c = lane; c < PS; c += 32) mx = fmaxf(mx, sbuf[r * PS + c]);
#pragma unroll
            for (int o = 16; o; o >>= 1) mx = fmaxf(mx, __shfl_xor_sync(0xffffffffu, mx, o));
            float sum = 0.0f;
            for (int c = lane; c < PS; c += 32) {
                const float e = __expf(sbuf[r * PS + c] - mx);
                sbuf[r * PS + c] = e;
                sum += e;
            }
#pragma unroll
            for (int o = 16; o; o >>= 1) sum += __shfl_xor_sync(0xffffffffu, sum, o);
            const float inv = 1.0f / sum;
            for (int c = lane; c < PS; c += 32)
                prob[pbase + (size_t)r * PS + c] = w0 * (sbuf[r * PS + c] * inv)
                                                 + l1 * relp[r * PS + c];
        }
        __syncthreads();
    }
}

// ---------------------------------------------------------------------------
// Kernel 3: out = prob @ V per (b,h). (unchanged)
// ---------------------------------------------------------------------------
__global__ __launch_bounds__(256, 2) void pv_kernel(const float* __restrict__ prob,
                                                    float* __restrict__ outp)
{
    __shared__ __align__(16) float pt[32][136];
    __shared__ __align__(16) float vt[32][64];

    const int bh = blockIdx.y;
    const int b = bh / PH, h = bh % PH;
    const int q0 = blockIdx.x * 128;
    const int tid = threadIdx.x;
    const int ng = tid & 15, qg = tid >> 4;

    uint64_t acc2[4][4];
#pragma unroll
    for (int i = 0; i < 4; i++)
#pragma unroll
        for (int j = 0; j < 4; j++) acc2[i][j] = 0ull;

    const size_t pbase = ((size_t)bh * PS + q0) * PS;
    const size_t vbase = (size_t)bh * PS * PHD;

    for (int kc0 = 0; kc0 < PS; kc0 += 32) {
        __syncthreads();
#pragma unroll
        for (int it = 0; it < 4; it++) {
            const int i4 = tid + it * 256;
            const int q = i4 >> 3, kq = (i4 & 7) << 2;
            const float4 v = *(const float4*)(prob + pbase + (size_t)q * PS + kc0 + kq);
            pt[kq + 0][q] = v.x; pt[kq + 1][q] = v.y;
            pt[kq + 2][q] = v.z; pt[kq + 3][q] = v.w;
        }
#pragma unroll
        for (int it = 0; it < 2; it++) {
            const int i4 = tid + it * 256;
            const int kr = i4 >> 4, n = (i4 & 15) << 2;
            *(float4*)&vt[kr][n] = *(const float4*)(g_v + vbase + (size_t)(kc0 + kr) * PHD + n);
        }
        __syncthreads();
#pragma unroll 8
        for (int kk = 0; kk < 32; kk++) {
            const ulonglong2 p01 = *(const ulonglong2*)&pt[kk][qg * 8];
            const ulonglong2 p23 = *(const ulonglong2*)&pt[kk][qg * 8 + 4];
            float vv[4];
            *(float4*)&vv[0] = *(const float4*)&vt[kk][ng * 4];
#pragma unroll
            for (int j = 0; j < 4; j++) {
                const uint64_t dv = dupf(vv[j]);
                ffma2(acc2[0][j], p01.x, dv);
                ffma2(acc2[1][j], p01.y, dv);
                ffma2(acc2[2][j], p23.x, dv);
                ffma2(acc2[3][j], p23.y, dv);
            }
        }
    }
#pragma unroll
    for (int ip = 0; ip < 4; ip++) {
        float o0[4], o1[4];
#pragma unroll
        for (int j = 0; j < 4; j++) {
            const float2 u = unpack2(acc2[ip][j]);
            o0[j] = u.x; o1[j] = u.y;
        }
        const int q = q0 + qg * 8 + ip * 2;
        *(float4*)&outp[((size_t)b * PS + q) * PD + h * PHD + ng * 4]     = *(float4*)o0;
        *(float4*)&outp[((size_t)b * PS + q + 1) * PD + h * PHD + ng * 4] = *(float4*)o1;
    }
}

// ---------------------------------------------------------------------------
extern "C" void kernel_launch(void* const* d_in, const int* in_sizes, int n_in,
                              void* d_out, int out_size) {
    const float* query = (const float*)d_in[0];
    const float* key   = (const float*)d_in[1];
    const float* value = (const float*)d_in[2];
    const float* rel   = (const float*)d_in[3];
    const void*  mask  = d_in[4];
    const float* l1    = (const float*)d_in[5];
    const float* Wq    = (const float*)d_in[6];
    const float* bq    = (const float*)d_in[7];
    const float* Wk    = (const float*)d_in[8];
    const float* bk    = (const float*)d_in[9];
    const float* Wv    = (const float*)d_in[10];
    const float* bv    = (const float*)d_in[11];

    float* outp = (float*)d_out;
    float* prob = outp + OUT_ELEMS;

    detect_mask_kernel<<<1, 256>>>(mask);

    conv_x_kernel<<<dim3((unsigned)(XE / 512), 3), 256>>>(query, key, value);
    conv_w_kernel<<<dim3((unsigned)(WE / 512), 3), 256>>>(Wq, Wk, Wv);

    cudaFuncSetAttribute(proj_mma_kernel,
                         cudaFuncAttributeMaxDynamicSharedMemorySize, PROJ_SMEM);
    dim3 g1(PD / 128, (PB * PS) / 128, 3);     // (6, 64, 3)
    proj_mma_kernel<<<g1, 256, PROJ_SMEM>>>(bq, bk, bv);

    cudaFuncSetAttribute(attn_scores_kernel,
                         cudaFuncAttributeMaxDynamicSharedMemorySize, (int)K2_SMEM);
    dim3 g2(PS / QT, PB);                      // (64, 8)
    attn_scores_kernel<<<g2, 256, K2_SMEM>>>(rel, mask, l1, prob);

    dim3 g3(PS / 128, PB * PH);                // (8, 96)
    pv_kernel<<<g3, 256>>>(prob, outp);
}

// round 8
// speedup vs baseline: 1.4964x; 1.2358x over previous
#include <cuda_runtime.h>
#include <cuda_bf16.h>
#include <cstdint>
#include <cstddef>

// Problem constants
constexpr int PB = 8, PS = 1024, PD = 768, PH = 12, PHD = 64;
constexpr size_t QKV_ELEMS = (size_t)PB * PH * PS * PHD;        // 6,291,456
constexpr size_t OUT_ELEMS = (size_t)PB * PS * PD;              // 6,291,456
constexpr size_t XE = (size_t)PB * PS * PD;                     // per matrix
constexpr size_t WE = (size_t)PD * PD;                          // per matrix
constexpr size_t RELP_ELEMS = (size_t)PB * PS * PS;             // 8,388,608

// Scratch (no allocations allowed -> __device__ globals)
__device__ __nv_bfloat16 g_xhi[3 * XE];
__device__ __nv_bfloat16 g_xlo[3 * XE];
__device__ __nv_bfloat16 g_whi[3 * WE];
__device__ __nv_bfloat16 g_wlo[3 * WE];
__device__ __nv_bfloat16 g_qhi[QKV_ELEMS], g_qlo[QKV_ELEMS];
__device__ __nv_bfloat16 g_khi[QKV_ELEMS], g_klo[QKV_ELEMS];
__device__ __nv_bfloat16 g_vhi[QKV_ELEMS], g_vlo[QKV_ELEMS];
__device__ __nv_bfloat16 g_vthi[QKV_ELEMS], g_vtlo[QKV_ELEMS];   // [b][h][hd][s]
__device__ float g_relp[RELP_ELEMS];
__device__ int   g_mask_mode;   // 0 = uint8/bool, 1 = int32, 2 = float32

// ---------------------------------------------------------------------------
// Tensor-core helpers (portable sm_80+ path: ldmatrix + mma.sync bf16)
// ---------------------------------------------------------------------------
__device__ __forceinline__ uint32_t smem_to_u32(const void* p) {
    uint32_t a;
    asm("{ .reg .u64 t; cvta.to.shared.u64 t, %1; cvt.u32.u64 %0, t; }" : "=r"(a) : "l"(p));
    return a;
}
__device__ __forceinline__ void ldmx4(uint32_t* r, uint32_t addr) {
    asm volatile("ldmatrix.sync.aligned.m8n8.x4.shared.b16 {%0,%1,%2,%3}, [%4];"
        : "=r"(r[0]), "=r"(r[1]), "=r"(r[2]), "=r"(r[3]) : "r"(addr));
}
__device__ __forceinline__ void mma16816(float* c, const uint32_t* a, uint32_t b0, uint32_t b1) {
    asm volatile("mma.sync.aligned.m16n8k16.row.col.f32.bf16.bf16.f32 "
        "{%0,%1,%2,%3}, {%4,%5,%6,%7}, {%8,%9}, {%0,%1,%2,%3};"
        : "+f"(c[0]), "+f"(c[1]), "+f"(c[2]), "+f"(c[3])
        : "r"(a[0]), "r"(a[1]), "r"(a[2]), "r"(a[3]), "r"(b0), "r"(b1));
}
#define SWZ128(off) ((off) ^ (((off) >> 3) & 0x70))

// ---------------------------------------------------------------------------
// Mask dtype probe (deterministic)
// ---------------------------------------------------------------------------
__global__ void detect_mask_kernel(const void* __restrict__ mask) {
    __shared__ int sawFloat, sawOther;
    if (threadIdx.x == 0) { sawFloat = 0; sawOther = 0; }
    __syncthreads();
    const unsigned int* w = (const unsigned int*)mask;
    int lf = 0, lo = 0;
    for (int i = threadIdx.x; i < 2048; i += blockDim.x) {
        unsigned int x = w[i];
        if (x == 0x3F800000u) lf = 1;
        else if (x > 1u) lo = 1;
    }
    if (lf) atomicOr(&sawFloat, 1);
    if (lo) atomicOr(&sawOther, 1);
    __syncthreads();
    if (threadIdx.x == 0) g_mask_mode = sawFloat ? 2 : (sawOther ? 0 : 1);
}

__device__ __forceinline__ bool read_mask(const void* m, size_t idx, int mode) {
    if (mode == 0) return ((const unsigned char*)m)[idx] != 0;
    if (mode == 1) return ((const int*)m)[idx] != 0;
    return ((const float*)m)[idx] != 0.0f;
}

// ---------------------------------------------------------------------------
// Conversion kernels: fp32 -> (bf16 hi, bf16 lo) split
// ---------------------------------------------------------------------------
__global__ void conv_x_kernel(const float* __restrict__ q, const float* __restrict__ k,
                              const float* __restrict__ v) {
    const int z = blockIdx.y;
    const float* src = (z == 0) ? q : (z == 1) ? k : v;
    __nv_bfloat16* hi = g_xhi + (size_t)z * XE;
    __nv_bfloat16* lo = g_xlo + (size_t)z * XE;
    const size_t i2 = ((size_t)blockIdx.x * blockDim.x + threadIdx.x) * 2;
    if (i2 + 1 >= XE) return;
    const float2 s = *(const float2*)(src + i2);
    const __nv_bfloat16 h0 = __float2bfloat16_rn(s.x);
    const __nv_bfloat16 h1 = __float2bfloat16_rn(s.y);
    *(__nv_bfloat162*)(hi + i2) = __halves2bfloat162(h0, h1);
    *(__nv_bfloat162*)(lo + i2) = __floats2bfloat162_rn(
        s.x - __bfloat162float(h0), s.y - __bfloat162float(h1));
}

__global__ void conv_w_kernel(const float* __restrict__ wq, const float* __restrict__ wk,
                              const float* __restrict__ wv) {
    const int z = blockIdx.y;
    const float* src = (z == 0) ? wq : (z == 1) ? wk : wv;
    __nv_bfloat16* hi = g_whi + (size_t)z * WE;
    __nv_bfloat16* lo = g_wlo + (size_t)z * WE;
    const size_t i2 = ((size_t)blockIdx.x * blockDim.x + threadIdx.x) * 2;
    if (i2 + 1 >= WE) return;
    const float2 s = *(const float2*)(src + i2);
    const __nv_bfloat16 h0 = __float2bfloat16_rn(s.x);
    const __nv_bfloat16 h1 = __float2bfloat16_rn(s.y);
    *(__nv_bfloat162*)(hi + i2) = __halves2bfloat162(h0, h1);
    *(__nv_bfloat162*)(lo + i2) = __floats2bfloat162_rn(
        s.x - __bfloat162float(h0), s.y - __bfloat162float(h1));
}

// ---------------------------------------------------------------------------
// relp kernel: rel_attn = softmax(where(rel*mask==0, -1e4, rel*mask)) per row.
// One warp per row, row held in registers (32 f32/lane).
// ---------------------------------------------------------------------------
__global__ void relp_kernel(const float* __restrict__ rel, const void* __restrict__ mask) {
    const int lane = threadIdx.x & 31;
    const int warp = threadIdx.x >> 5;
    const int row = blockIdx.x * 8 + warp;          // 0..8191 = b*1024+s
    const size_t rbase = (size_t)row * PS;
    const int mmode = g_mask_mode;
    float vals[32];
    float mx = -3.0e38f;
#pragma unroll
    for (int i = 0; i < 32; i++) {
        const int c = lane + i * 32;
        const bool m = read_mask(mask, rbase + c, mmode);
        const float v = rel[rbase + c];
        const float relm = m ? v : 0.0f;
        const float logit = (relm == 0.0f) ? -10000.0f : relm;
        vals[i] = logit;
        mx = fmaxf(mx, logit);
    }
#pragma unroll
    for (int o = 16; o; o >>= 1) mx = fmaxf(mx, __shfl_xor_sync(0xffffffffu, mx, o));
    float sum = 0.0f;
#pragma unroll
    for (int i = 0; i < 32; i++) { vals[i] = __expf(vals[i] - mx); sum += vals[i]; }
#pragma unroll
    for (int o = 16; o; o >>= 1) sum += __shfl_xor_sync(0xffffffffu, sum, o);
    const float inv = 1.0f / sum;
#pragma unroll
    for (int i = 0; i < 32; i++) g_relp[rbase + lane + i * 32] = vals[i] * inv;
}

// ---------------------------------------------------------------------------
// Kernel 1: HMMA bf16-split projection GEMM (epilogue now emits bf16 hi/lo).
// ---------------------------------------------------------------------------
constexpr int PROJ_SMEM = 4 * 16384;   // 64KB dynamic

__device__ __forceinline__ void load_slab_part(const __nv_bfloat16* __restrict__ src,
                                               int row0, int k0, char* dst, int tid) {
#pragma unroll
    for (int it = 0; it < 4; it++) {
        const int c = tid + it * 256;          // 0..1023 16B-chunks
        const int r = c >> 3;                  // 0..127
        const int e8 = (c & 7) * 8;            // bf16 element offset in row
        const uint4 v = *(const uint4*)(src + (size_t)(row0 + r) * PD + k0 + e8);
        *(uint4*)(dst + SWZ128(r * 128 + e8 * 2)) = v;
    }
}

__global__ __launch_bounds__(256, 2)
void proj_mma_kernel(const float* __restrict__ bq, const float* __restrict__ bk,
                     const float* __restrict__ bv)
{
    extern __shared__ char sm[];
    __shared__ float bias_s[128];

    const int tid  = threadIdx.x;
    const int warp = tid >> 5;
    const int lane = tid & 31;
    const int wm = warp >> 2;      // 0..1 -> 64 rows each
    const int wn = warp & 3;       // 0..3 -> 32 cols each
    const int z  = blockIdx.z;
    const int n0 = blockIdx.x * 128;
    const int m0 = blockIdx.y * 128;

    const __nv_bfloat16* xhi = g_xhi + (size_t)z * XE;
    const __nv_bfloat16* xlo = g_xlo + (size_t)z * XE;
    const __nv_bfloat16* whi = g_whi + (size_t)z * WE;
    const __nv_bfloat16* wlo = g_wlo + (size_t)z * WE;
    const float* bias = (z == 0) ? bq : (z == 1) ? bk : bv;
    __nv_bfloat16* ohi = (z == 0) ? g_qhi : (z == 1) ? g_khi : g_vhi;
    __nv_bfloat16* olo = (z == 0) ? g_qlo : (z == 1) ? g_klo : g_vlo;

    if (tid < 128) bias_s[tid] = bias[n0 + tid];

    char* Ahi_s = sm;
    char* Alo_s = sm + 16384;
    char* Bhi_s = sm + 32768;
    char* Blo_s = sm + 49152;
    const uint32_t uAhi = smem_to_u32(Ahi_s);
    const uint32_t uAlo = smem_to_u32(Alo_s);
    const uint32_t uBhi = smem_to_u32(Bhi_s);
    const uint32_t uBlo = smem_to_u32(Blo_s);

    float acc[4][4][4];
#pragma unroll
    for (int i = 0; i < 4; i++)
#pragma unroll
        for (int j = 0; j < 4; j++)
#pragma unroll
            for (int c = 0; c < 4; c++) acc[i][j][c] = 0.0f;

    const int lrow  = lane & 15;
    const int lcolb = (lane >> 4) * 16;

    for (int s = 0; s < 12; s++) {
        __syncthreads();
        const int k0 = s * 64;
        load_slab_part(xhi, m0, k0, Ahi_s, tid);
        load_slab_part(xlo, m0, k0, Alo_s, tid);
        load_slab_part(whi, n0, k0, Bhi_s, tid);
        load_slab_part(wlo, n0, k0, Blo_s, tid);
        __syncthreads();
#pragma unroll
        for (int ks = 0; ks < 4; ks++) {
            const int kb = ks * 32 + lcolb;
            uint32_t bhi[2][4], blo[2][4];
#pragma unroll
            for (int nt2 = 0; nt2 < 2; nt2++) {
                const int brow = wn * 32 + nt2 * 16 + lrow;
                ldmx4(bhi[nt2], uBhi + SWZ128(brow * 128 + kb));
                ldmx4(blo[nt2], uBlo + SWZ128(brow * 128 + kb));
            }
#pragma unroll
            for (int mt = 0; mt < 4; mt++) {
                const int arow = wm * 64 + mt * 16 + lrow;
                uint32_t a[4];
                ldmx4(a, uAhi + SWZ128(arow * 128 + kb));       // Ahi
#pragma unroll
                for (int nt2 = 0; nt2 < 2; nt2++)
#pragma unroll
                    for (int j = 0; j < 2; j++) {
                        mma16816(acc[mt][nt2 * 2 + j], a, bhi[nt2][j], bhi[nt2][2 + j]);
                        mma16816(acc[mt][nt2 * 2 + j], a, blo[nt2][j], blo[nt2][2 + j]);
                    }
                ldmx4(a, uAlo + SWZ128(arow * 128 + kb));       // Alo
#pragma unroll
                for (int nt2 = 0; nt2 < 2; nt2++)
#pragma unroll
                    for (int j = 0; j < 2; j++)
                        mma16816(acc[mt][nt2 * 2 + j], a, bhi[nt2][j], bhi[nt2][2 + j]);
            }
        }
    }

    // Epilogue: +bias, split to bf16 hi/lo, scatter [b][h][s][hd]
    const int g   = lane >> 2;
    const int tg2 = (lane & 3) * 2;
#pragma unroll
    for (int mt = 0; mt < 4; mt++) {
#pragma unroll
        for (int nt = 0; nt < 4; nt++) {
            const int nc = wn * 32 + nt * 8 + tg2;
            const int n = n0 + nc;
            const int h = n >> 6, hd = n & 63;
            const int m = m0 + wm * 64 + mt * 16 + g;
            const int b = m >> 10, sq = m & 1023;
#pragma unroll
            for (int cc = 0; cc < 2; cc++) {           // cc=0: row sq; cc=1: row sq+8
                const float y0 = acc[mt][nt][cc * 2 + 0] + bias_s[nc];
                const float y1 = acc[mt][nt][cc * 2 + 1] + bias_s[nc + 1];
                const __nv_bfloat16 h0 = __float2bfloat16_rn(y0);
                const __nv_bfloat16 h1 = __float2bfloat16_rn(y1);
                const size_t di = (((size_t)(b * PH + h)) * PS + sq + cc * 8) * PHD + hd;
                *(__nv_bfloat162*)(ohi + di) = __halves2bfloat162(h0, h1);
                *(__nv_bfloat162*)(olo + di) = __floats2bfloat162_rn(
                    y0 - __bfloat162float(h0), y1 - __bfloat162float(h1));
            }
        }
    }
}

// ---------------------------------------------------------------------------
// V transpose: [b][h][s][hd] -> [b][h][hd][s] (hi and lo)
// ---------------------------------------------------------------------------
__global__ void vtrans_kernel() {
    __shared__ __nv_bfloat16 th[64][65], tl[64][65];
    const int tid = threadIdx.x;
    const int bh = blockIdx.y;
    const int st = blockIdx.x * 64;
    const size_t src0 = ((size_t)bh * PS + st) * PHD;
#pragma unroll
    for (int it = 0; it < 16; it++) {
        const int i = tid + it * 256;      // 0..4095
        const int s = i >> 6, hd = i & 63;
        th[hd][s] = g_vhi[src0 + (size_t)s * PHD + hd];
        tl[hd][s] = g_vlo[src0 + (size_t)s * PHD + hd];
    }
    __syncthreads();
    const size_t dst0 = (size_t)bh * PHD * PS + st;
#pragma unroll
    for (int it = 0; it < 16; it++) {
        const int i = tid + it * 256;
        const int hd = i >> 6, s = i & 63;
        g_vthi[dst0 + (size_t)hd * PS + s] = th[hd][s];
        g_vtlo[dst0 + (size_t)hd * PS + s] = tl[hd][s];
    }
}

// ---------------------------------------------------------------------------
// Kernel 2: HMMA scores. Per CTA: (b,h), 32 q-rows. QK^T/8 masked -> smem,
// softmax (register rows), combine with g_relp, write prob.
// smem: sbuf f32[32][1028] @0 (131584), qhi@131584(4096), qlo@135680(4096),
//       khi@139776(16384), klo@156160(16384), msk@172544(32768) = 205312
// ---------------------------------------------------------------------------
constexpr int SC_SMEM = 205312;
constexpr int SC_QHI = 131584, SC_QLO = 135680, SC_KHI = 139776, SC_KLO = 156160,
              SC_MSK = 172544;

__global__ __launch_bounds__(256, 1)
void scores_mma_kernel(const void* __restrict__ mask, const float* __restrict__ l1p,
                       float* __restrict__ prob)
{
    extern __shared__ char sm2[];
    float* sbuf = (float*)sm2;
    char* qhi_s = sm2 + SC_QHI;
    char* qlo_s = sm2 + SC_QLO;
    char* khi_s = sm2 + SC_KHI;
    char* klo_s = sm2 + SC_KLO;
    unsigned char* msk = (unsigned char*)(sm2 + SC_MSK);
    const uint32_t uQhi = smem_to_u32(qhi_s);
    const uint32_t uQlo = smem_to_u32(qlo_s);
    const uint32_t uKhi = smem_to_u32(khi_s);
    const uint32_t uKlo = smem_to_u32(klo_s);

    const int tid  = threadIdx.x;
    const int warp = tid >> 5;
    const int lane = tid & 31;
    const int wm = warp >> 2;          // 0..1 (16 rows)
    const int wn = warp & 3;           // 0..3 (32 cols)
    const int bh = blockIdx.y;
    const int b = bh / PH, h = bh % PH;
    const int q0 = blockIdx.x * 32;
    const int mmode = g_mask_mode;
    const float l1 = *l1p;
    const float w0 = 1.0f - l1;

    // mask tile -> smem bytes
    const size_t mrow = ((size_t)b * PS + q0) * PS;
    for (int i = tid; i < 32 * 1024; i += 256)
        msk[i] = read_mask(mask, mrow + i, mmode) ? 1 : 0;

    // Q tile (32 x 64), hi+lo: 256 16B-chunks each, 1 per thread
    {
        const size_t qoff = ((size_t)bh * PS + q0) * PHD;
        const int r = tid >> 3, e8 = (tid & 7) * 8;
        *(uint4*)(qhi_s + SWZ128(r * 128 + e8 * 2)) =
            *(const uint4*)(g_qhi + qoff + (size_t)r * PHD + e8);
        *(uint4*)(qlo_s + SWZ128(r * 128 + e8 * 2)) =
            *(const uint4*)(g_qlo + qoff + (size_t)r * PHD + e8);
    }

    const int lrow  = lane & 15;
    const int lcolb = (lane >> 4) * 16;
    const int g   = lane >> 2;
    const int tg2 = (lane & 3) * 2;
    const size_t kbh = (size_t)bh * PS * PHD;

    for (int kc0 = 0; kc0 < PS; kc0 += 128) {
        __syncthreads();
        // K slab 128 x 64, hi+lo
#pragma unroll
        for (int it = 0; it < 4; it++) {
            const int c = tid + it * 256;
            const int r = c >> 3, e8 = (c & 7) * 8;
            *(uint4*)(khi_s + SWZ128(r * 128 + e8 * 2)) =
                *(const uint4*)(g_khi + kbh + (size_t)(kc0 + r) * PHD + e8);
            *(uint4*)(klo_s + SWZ128(r * 128 + e8 * 2)) =
                *(const uint4*)(g_klo + kbh + (size_t)(kc0 + r) * PHD + e8);
        }
        __syncthreads();

        float acc[4][4];
#pragma unroll
        for (int i = 0; i < 4; i++)
#pragma unroll
            for (int c = 0; c < 4; c++) acc[i][c] = 0.0f;
#pragma unroll
        for (int ks = 0; ks < 4; ks++) {
            const int kb = ks * 32 + lcolb;
            uint32_t bhi[2][4], blo[2][4], ahi[4], alo[4];
#pragma unroll
            for (int nt2 = 0; nt2 < 2; nt2++) {
                const int brow = wn * 32 + nt2 * 16 + lrow;
                ldmx4(bhi[nt2], uKhi + SWZ128(brow * 128 + kb));
                ldmx4(blo[nt2], uKlo + SWZ128(brow * 128 + kb));
            }
            const int arow = wm * 16 + lrow;
            ldmx4(ahi, uQhi + SWZ128(arow * 128 + kb));
            ldmx4(alo, uQlo + SWZ128(arow * 128 + kb));
#pragma unroll
            for (int nt2 = 0; nt2 < 2; nt2++)
#pragma unroll
                for (int j = 0; j < 2; j++) {
                    mma16816(acc[nt2 * 2 + j], ahi, bhi[nt2][j], bhi[nt2][2 + j]);
                    mma16816(acc[nt2 * 2 + j], ahi, blo[nt2][j], blo[nt2][2 + j]);
                    mma16816(acc[nt2 * 2 + j], alo, bhi[nt2][j], bhi[nt2][2 + j]);
                }
        }
        // epilogue: mask + scale -> sbuf
        const int r0 = wm * 16 + g, r1 = r0 + 8;
#pragma unroll
        for (int nt = 0; nt < 4; nt++) {
            const int kcol = kc0 + wn * 32 + nt * 8 + tg2;
            const int mi0 = r0 * 1024 + kcol, mi1 = r1 * 1024 + kcol;
            sbuf[r0 * 1028 + kcol]     = msk[mi0]     ? -1.0e9f : acc[nt][0] * 0.125f;
            sbuf[r0 * 1028 + kcol + 1] = msk[mi0 + 1] ? -1.0e9f : acc[nt][1] * 0.125f;
            sbuf[r1 * 1028 + kcol]     = msk[mi1]     ? -1.0e9f : acc[nt][2] * 0.125f;
            sbuf[r1 * 1028 + kcol + 1] = msk[mi1 + 1] ? -1.0e9f : acc[nt][3] * 0.125f;
        }
    }
    __syncthreads();

    // softmax + combine + write. Warp handles rows warp*4..+3.
#pragma unroll
    for (int rr = 0; rr < 4; rr++) {
        const int r = warp * 4 + rr;
        float vals[32];
        float mx = -3.0e38f;
#pragma unroll
        for (int i = 0; i < 32; i++) {
            vals[i] = sbuf[r * 1028 + lane + i * 32];
            mx = fmaxf(mx, vals[i]);
        }
#pragma unroll
        for (int o = 16; o; o >>= 1) mx = fmaxf(mx, __shfl_xor_sync(0xffffffffu, mx, o));
        float sum = 0.0f;
#pragma unroll
        for (int i = 0; i < 32; i++) { vals[i] = __expf(vals[i] - mx); sum += vals[i]; }
#pragma unroll
        for (int o = 16; o; o >>= 1) sum += __shfl_xor_sync(0xffffffffu, sum, o);
        const float inv = 1.0f / sum;
        const size_t pb = (((size_t)(b * PH + h)) * PS + q0 + r) * PS;
        const float* rp = g_relp + ((size_t)b * PS + q0 + r) * PS;
#pragma unroll
        for (int i = 0; i < 32; i++) {
            const int c = lane + i * 32;
            prob[pb + c] = w0 * vals[i] * inv + l1 * rp[c];
        }
    }
}

// ---------------------------------------------------------------------------
// Kernel 3: HMMA pv. out = prob @ V per (b,h). CTA 128q x 64hd, K-slab 64.
// prob fp32 -> bf16 hi/lo split in-kernel; V from transposed [hd][s] tiles.
// smem: phi@0(16K), plo@16K, vhi@32K(8K), vlo@40K(8K) = 48KB
// ---------------------------------------------------------------------------
constexpr int PV_SMEM = 49152;

__global__ __launch_bounds__(256, 2)
void pv_mma_kernel(const float* __restrict__ prob, float* __restrict__ outp)
{
    extern __shared__ char sm3[];
    char* phi_s = sm3;
    char* plo_s = sm3 + 16384;
    char* vhi_s = sm3 + 32768;
    char* vlo_s = sm3 + 40960;
    const uint32_t uPhi = smem_to_u32(phi_s);
    const uint32_t uPlo = smem_to_u32(plo_s);
    const uint32_t uVhi = smem_to_u32(vhi_s);
    const uint32_t uVlo = smem_to_u32(vlo_s);

    const int tid  = threadIdx.x;
    const int warp = tid >> 5;
    const int lane = tid & 31;
    const int wm = warp >> 1;          // 0..3 (32 q rows)
    const int wn = warp & 1;           // 0..1 (32 hd cols)
    const int bh = blockIdx.y;
    const int b = bh / PH, h = bh % PH;
    const int q0 = blockIdx.x * 128;

    const size_t pbase = ((size_t)bh * PS + q0) * PS;
    const size_t vtb = (size_t)bh * PHD * PS;

    float acc[2][4][4];
#pragma unroll
    for (int i = 0; i < 2; i++)
#pragma unroll
        for (int j = 0; j < 4; j++)
#pragma unroll
            for (int c = 0; c < 4; c++) acc[i][j][c] = 0.0f;

    const int lrow  = lane & 15;
    const int lcolb = (lane >> 4) * 16;

    for (int kc0 = 0; kc0 < PS; kc0 += 64) {
        __syncthreads();
        // prob tile [128 q][64 k] fp32 -> bf16 hi/lo swizzled
#pragma unroll
        for (int it = 0; it < 8; it++) {
            const int c = tid + it * 256;          // 0..2047 float4 chunks
            const int q = c >> 4, k4 = (c & 15) * 4;
            const float4 v = *(const float4*)(prob + pbase + (size_t)q * PS + kc0 + k4);
            const __nv_bfloat16 h0 = __float2bfloat16_rn(v.x);
            const __nv_bfloat16 h1 = __float2bfloat16_rn(v.y);
            const __nv_bfloat16 h2 = __float2bfloat16_rn(v.z);
            const __nv_bfloat16 h3 = __float2bfloat16_rn(v.w);
            __nv_bfloat162 hp01 = __halves2bfloat162(h0, h1);
            __nv_bfloat162 hp23 = __halves2bfloat162(h2, h3);
            __nv_bfloat162 lp01 = __floats2bfloat162_rn(v.x - __bfloat162float(h0),
                                                        v.y - __bfloat162float(h1));
            __nv_bfloat162 lp23 = __floats2bfloat162_rn(v.z - __bfloat162float(h2),
                                                        v.w - __bfloat162float(h3));
            uint2 hv, lv;
            hv.x = *reinterpret_cast<uint32_t*>(&hp01);
            hv.y = *reinterpret_cast<uint32_t*>(&hp23);
            lv.x = *reinterpret_cast<uint32_t*>(&lp01);
            lv.y = *reinterpret_cast<uint32_t*>(&lp23);
            *(uint2*)(phi_s + SWZ128(q * 128 + k4 * 2)) = hv;
            *(uint2*)(plo_s + SWZ128(q * 128 + k4 * 2)) = lv;
        }
        // vT slab [64 hd][64 k]
#pragma unroll
        for (int it = 0; it < 2; it++) {
            const int c = tid + it * 256;          // 0..511 16B chunks
            const int r = c >> 3, e8 = (c & 7) * 8;
            *(uint4*)(vhi_s + SWZ128(r * 128 + e8 * 2)) =
                *(const uint4*)(g_vthi + vtb + (size_t)r * PS + kc0 + e8);
            *(uint4*)(vlo_s + SWZ128(r * 128 + e8 * 2)) =
                *(const uint4*)(g_vtlo + vtb + (size_t)r * PS + kc0 + e8);
        }
        __syncthreads();
#pragma unroll
        for (int ks = 0; ks < 4; ks++) {
            const int kb = ks * 32 + lcolb;
            uint32_t bhi[2][4], blo[2][4];
#pragma unroll
            for (int nt2 = 0; nt2 < 2; nt2++) {
                const int brow = wn * 32 + nt2 * 16 + lrow;
                ldmx4(bhi[nt2], uVhi + SWZ128(brow * 128 + kb));
                ldmx4(blo[nt2], uVlo + SWZ128(brow * 128 + kb));
            }
#pragma unroll
            for (int mt = 0; mt < 2; mt++) {
                const int arow = wm * 32 + mt * 16 + lrow;
                uint32_t a[4];
                ldmx4(a, uPhi + SWZ128(arow * 128 + kb));
#pragma unroll
                for (int nt2 = 0; nt2 < 2; nt2++)
#pragma unroll
                    for (int j = 0; j < 2; j++) {
                        mma16816(acc[mt][nt2 * 2 + j], a, bhi[nt2][j], bhi[nt2][2 + j]);
                        mma16816(acc[mt][nt2 * 2 + j], a, blo[nt2][j], blo[nt2][2 + j]);
                    }
                ldmx4(a, uPlo + SWZ128(arow * 128 + kb));
#pragma unroll
                for (int nt2 = 0; nt2 < 2; nt2++)
#pragma unroll
                    for (int j = 0; j < 2; j++)
                        mma16816(acc[mt][nt2 * 2 + j], a, bhi[nt2][j], bhi[nt2][2 + j]);
            }
        }
    }
    // epilogue
    const int g   = lane >> 2;
    const int tg2 = (lane & 3) * 2;
#pragma unroll
    for (int mt = 0; mt < 2; mt++) {
#pragma unroll
        for (int nt = 0; nt < 4; nt++) {
            const int nc = wn * 32 + nt * 8 + tg2;
            const int m = q0 + wm * 32 + mt * 16 + g;
            float2 v0, v1;
            v0.x = acc[mt][nt][0]; v0.y = acc[mt][nt][1];
            v1.x = acc[mt][nt][2]; v1.y = acc[mt][nt][3];
            *(float2*)(outp + ((size_t)b * PS + m) * PD + h * PHD + nc)     = v0;
            *(float2*)(outp + ((size_t)b * PS + m + 8) * PD + h * PHD + nc) = v1;
        }
    }
}

// ---------------------------------------------------------------------------
extern "C" void kernel_launch(void* const* d_in, const int* in_sizes, int n_in,
                              void* d_out, int out_size) {
    const float* query = (const float*)d_in[0];
    const float* key   = (const float*)d_in[1];
    const float* value = (const float*)d_in[2];
    const float* rel   = (const float*)d_in[3];
    const void*  mask  = d_in[4];
    const float* l1    = (const float*)d_in[5];
    const float* bq    = (const float*)d_in[7];
    const float* bk    = (const float*)d_in[9];
    const float* bv    = (const float*)d_in[11];
    const float* Wq    = (const float*)d_in[6];
    const float* Wk    = (const float*)d_in[8];
    const float* Wv    = (const float*)d_in[10];

    float* outp = (float*)d_out;
    float* prob = outp + OUT_ELEMS;

    detect_mask_kernel<<<1, 256>>>(mask);

    conv_x_kernel<<<dim3((unsigned)(XE / 512), 3), 256>>>(query, key, value);
    conv_w_kernel<<<dim3((unsigned)(WE / 512), 3), 256>>>(Wq, Wk, Wv);
    relp_kernel<<<1024, 256>>>(rel, mask);

    cudaFuncSetAttribute(proj_mma_kernel,
                         cudaFuncAttributeMaxDynamicSharedMemorySize, PROJ_SMEM);
    dim3 g1(PD / 128, (PB * PS) / 128, 3);     // (6, 64, 3)
    proj_mma_kernel<<<g1, 256, PROJ_SMEM>>>(bq, bk, bv);

    vtrans_kernel<<<dim3(16, PB * PH), 256>>>();

    cudaFuncSetAttribute(scores_mma_kernel,
                         cudaFuncAttributeMaxDynamicSharedMemorySize, SC_SMEM);
    dim3 g2(PS / 32, PB * PH);                 // (32, 96)
    scores_mma_kernel<<<g2, 256, SC_SMEM>>>(mask, l1, prob);

    cudaFuncSetAttribute(pv_mma_kernel,
                         cudaFuncAttributeMaxDynamicSharedMemorySize, PV_SMEM);
    dim3 g3(PS / 128, PB * PH);                // (8, 96)
    pv_mma_kernel<<<g3, 256, PV_SMEM>>>(prob, outp);
}